// round 1
// baseline (speedup 1.0000x reference)
#include <cuda_runtime.h>
#include <cstdint>

#define N_NODES   50000
#define N_EDGES   1600000
#define N_GRAPHS  128
#define IN_CH     64
#define EDGE_DIM  16
#define HID       64
#define N_CLASSES 10
#define N_LAYERS  5
#define BN_EPS    1e-5f

// ---------------- scratch (device globals; no allocations allowed) -------
__device__ __align__(16) float g_h[N_NODES * HID];       // node features
__device__ __align__(16) float g_z[N_NODES * HID];       // (1+eps)h + aggr
__device__ __align__(16) float g_zout[N_NODES * HID];    // MLP output
__device__ __align__(16) float g_e[(size_t)N_EDGES * HID]; // edge proj (409MB)
__device__ __align__(16) float g_stats[2 * HID];         // sum, sumsq
__device__ __align__(16) float g_bn[2 * HID];            // mu, inv_std
__device__ __align__(16) float g_pool[N_GRAPHS * HID];
__device__ __align__(16) float g_cnt[N_GRAPHS];

// ---------------- kernels ------------------------------------------------

// h = x @ Wn + bn ; one thread per (node, channel)
__global__ void k_node_proj(const float* __restrict__ x,
                            const float* __restrict__ Wn,
                            const float* __restrict__ bn) {
    __shared__ float Ws[IN_CH * HID];
    __shared__ float bs[HID];
    int t = threadIdx.x;
    for (int i = t; i < IN_CH * HID; i += blockDim.x) Ws[i] = Wn[i];
    if (t < HID) bs[t] = bn[t];
    __syncthreads();
    int gid = blockIdx.x * blockDim.x + t;
    if (gid >= N_NODES * HID) return;
    int n = gid >> 6, c = gid & 63;
    float acc = bs[c];
    const float* xr = x + (size_t)n * IN_CH;
#pragma unroll 16
    for (int k = 0; k < IN_CH; k++) acc += xr[k] * Ws[k * HID + c];
    g_h[gid] = acc;
}

// e = edge_attr @ We + be ; one thread per (edge, 4 channels)
__global__ void k_edge_proj(const float* __restrict__ ea,
                            const float* __restrict__ We,
                            const float* __restrict__ be) {
    __shared__ float Ws[EDGE_DIM * HID];
    __shared__ float bs[HID];
    int t = threadIdx.x;
    for (int i = t; i < EDGE_DIM * HID; i += blockDim.x) Ws[i] = We[i];
    if (t < HID) bs[t] = be[t];
    __syncthreads();
    int gid = blockIdx.x * blockDim.x + t;
    if (gid >= N_EDGES * 16) return;
    int edge = gid >> 4, q = gid & 15;
    int c = q * 4;
    float a0 = bs[c], a1 = bs[c + 1], a2 = bs[c + 2], a3 = bs[c + 3];
    const float* er = ea + (size_t)edge * EDGE_DIM;
#pragma unroll
    for (int k = 0; k < EDGE_DIM; k++) {
        float v = er[k];
        const float* wr = Ws + k * HID + c;
        a0 += v * wr[0]; a1 += v * wr[1]; a2 += v * wr[2]; a3 += v * wr[3];
    }
    float4 r = make_float4(a0, a1, a2, a3);
    *reinterpret_cast<float4*>(&g_e[(size_t)edge * HID + c]) = r;
}

// z = (1+eps_l) * h ; also zero the stats buffer
__global__ void k_pre(const float* __restrict__ eps, int layer) {
    int gid = blockIdx.x * blockDim.x + threadIdx.x;
    if (blockIdx.x == 0 && threadIdx.x < 2 * HID) g_stats[threadIdx.x] = 0.0f;
    if (gid >= N_NODES * HID) return;
    float s = 1.0f + eps[layer];
    g_z[gid] = s * g_h[gid];
}

// message + scatter: z[dst] += relu(h[src] + e) ; 16 threads/edge, float4
__global__ void k_msg(const int* __restrict__ ei) {
    int gid = blockIdx.x * blockDim.x + threadIdx.x;
    if (gid >= N_EDGES * 16) return;
    int edge = gid >> 4, q = gid & 15;
    int c = q * 4;
    int src = ei[edge];
    int dst = ei[N_EDGES + edge];
    float4 e4 = *reinterpret_cast<const float4*>(&g_e[(size_t)edge * HID + c]);
    float4 h4 = *reinterpret_cast<const float4*>(&g_h[(size_t)src * HID + c]);
    float m0 = fmaxf(h4.x + e4.x, 0.0f);
    float m1 = fmaxf(h4.y + e4.y, 0.0f);
    float m2 = fmaxf(h4.z + e4.z, 0.0f);
    float m3 = fmaxf(h4.w + e4.w, 0.0f);
    float* p = &g_z[(size_t)dst * HID + c];
    asm volatile("red.global.add.v4.f32 [%0], {%1, %2, %3, %4};"
                 :: "l"(p), "f"(m0), "f"(m1), "f"(m2), "f"(m3) : "memory");
}

// MLP: zout = relu(z @ W1 + b1) @ W2 + b2 ; one warp per node.
// Accumulate per-channel sum / sumsq for BN (smem then global atomics).
__global__ void k_mlp(const float* __restrict__ W1, const float* __restrict__ b1,
                      const float* __restrict__ W2, const float* __restrict__ b2) {
    __shared__ float W1s[HID * HID];
    __shared__ float W2s[HID * HID];
    __shared__ float b1s[HID], b2s[HID];
    __shared__ float ssum[HID], ssq[HID];
    int t = threadIdx.x;
    for (int i = t; i < HID * HID; i += blockDim.x) { W1s[i] = W1[i]; W2s[i] = W2[i]; }
    if (t < HID) { b1s[t] = b1[t]; b2s[t] = b2[t]; ssum[t] = 0.0f; ssq[t] = 0.0f; }
    __syncthreads();

    int warp = t >> 5, lane = t & 31;
    int node = blockIdx.x * (blockDim.x >> 5) + warp;
    float o0 = 0.0f, o1 = 0.0f;
    if (node < N_NODES) {
        const float* zr = g_z + (size_t)node * HID;
        float z0 = zr[lane], z1 = zr[32 + lane];
        float a0 = b1s[lane], a1 = b1s[32 + lane];
#pragma unroll
        for (int k = 0; k < 32; k++) {
            float zk = __shfl_sync(0xffffffffu, z0, k);
            a0 += zk * W1s[k * HID + lane];
            a1 += zk * W1s[k * HID + 32 + lane];
        }
#pragma unroll
        for (int k = 0; k < 32; k++) {
            float zk = __shfl_sync(0xffffffffu, z1, k);
            a0 += zk * W1s[(32 + k) * HID + lane];
            a1 += zk * W1s[(32 + k) * HID + 32 + lane];
        }
        a0 = fmaxf(a0, 0.0f); a1 = fmaxf(a1, 0.0f);
        o0 = b2s[lane]; o1 = b2s[32 + lane];
#pragma unroll
        for (int k = 0; k < 32; k++) {
            float ak = __shfl_sync(0xffffffffu, a0, k);
            o0 += ak * W2s[k * HID + lane];
            o1 += ak * W2s[k * HID + 32 + lane];
        }
#pragma unroll
        for (int k = 0; k < 32; k++) {
            float ak = __shfl_sync(0xffffffffu, a1, k);
            o0 += ak * W2s[(32 + k) * HID + lane];
            o1 += ak * W2s[(32 + k) * HID + 32 + lane];
        }
        float* zo = g_zout + (size_t)node * HID;
        zo[lane] = o0; zo[32 + lane] = o1;
    }
    atomicAdd(&ssum[lane], o0);       atomicAdd(&ssq[lane], o0 * o0);
    atomicAdd(&ssum[32 + lane], o1);  atomicAdd(&ssq[32 + lane], o1 * o1);
    __syncthreads();
    if (t < HID) {
        atomicAdd(&g_stats[t], ssum[t]);
        atomicAdd(&g_stats[HID + t], ssq[t]);
    }
}

// finalize BN stats
__global__ void k_bnfin() {
    int t = threadIdx.x;
    if (t >= HID) return;
    float invN = 1.0f / (float)N_NODES;
    float mu = g_stats[t] * invN;
    float var = g_stats[HID + t] * invN - mu * mu;
    g_bn[t] = mu;
    g_bn[HID + t] = rsqrtf(var + BN_EPS);
}

// h = relu(gamma*(zout - mu)*inv + beta) + h
__global__ void k_bnapply(const float* __restrict__ gamma,
                          const float* __restrict__ beta) {
    int gid = blockIdx.x * blockDim.x + threadIdx.x;
    if (gid >= N_NODES * HID) return;
    int c = gid & 63;
    float v = g_zout[gid];
    v = gamma[c] * (v - g_bn[c]) * g_bn[HID + c] + beta[c];
    g_h[gid] = fmaxf(v, 0.0f) + g_h[gid];
}

__global__ void k_pool_zero() {
    int gid = blockIdx.x * blockDim.x + threadIdx.x;
    if (gid < N_GRAPHS * HID) g_pool[gid] = 0.0f;
    if (gid < N_GRAPHS) g_cnt[gid] = 0.0f;
}

__global__ void k_pool(const int* __restrict__ batch) {
    int gid = blockIdx.x * blockDim.x + threadIdx.x;
    if (gid >= N_NODES * HID) return;
    int n = gid >> 6, c = gid & 63;
    int b = batch[n];
    atomicAdd(&g_pool[b * HID + c], g_h[gid]);
    if (c == 0) atomicAdd(&g_cnt[b], 1.0f);
}

// classifier: one thread per graph (128 threads, 1 block)
__global__ void k_cls(const float* __restrict__ W1, const float* __restrict__ b1,
                      const float* __restrict__ W2, const float* __restrict__ b2,
                      float* __restrict__ out) {
    int g = threadIdx.x;
    if (g >= N_GRAPHS) return;
    float cnt = fmaxf(g_cnt[g], 1.0f);
    float inv = 1.0f / cnt;
    float pr[HID];
#pragma unroll
    for (int k = 0; k < HID; k++) pr[k] = g_pool[g * HID + k] * inv;
    float a[HID];
#pragma unroll 4
    for (int j = 0; j < HID; j++) {
        float acc = b1[j];
        for (int k = 0; k < HID; k++) acc += pr[k] * W1[k * HID + j];
        a[j] = fmaxf(acc, 0.0f);
    }
#pragma unroll
    for (int j = 0; j < N_CLASSES; j++) {
        float acc = b2[j];
#pragma unroll 8
        for (int k = 0; k < HID; k++) acc += a[k] * W2[k * N_CLASSES + j];
        float prob = 1.0f / (1.0f + expf(-acc));
        float pred = (prob > 0.5f) ? 1.0f : 0.0f;
        int idx = g * N_CLASSES + j;
        out[idx] = acc;                               // logits
        out[N_GRAPHS * N_CLASSES + idx] = prob;       // probs
        out[2 * N_GRAPHS * N_CLASSES + idx] = pred;   // preds
        out[3 * N_GRAPHS * N_CLASSES + idx] = pred;   // preds (again)
    }
}

// ---------------- launch --------------------------------------------------
extern "C" void kernel_launch(void* const* d_in, const int* in_sizes, int n_in,
                              void* d_out, int out_size) {
    const float* x      = (const float*)d_in[0];
    const int*   ei     = (const int*)  d_in[1];
    const int*   batch  = (const int*)  d_in[2];
    const float* ea     = (const float*)d_in[3];
    const float* Wn     = (const float*)d_in[4];
    const float* bn     = (const float*)d_in[5];
    const float* We     = (const float*)d_in[6];
    const float* be     = (const float*)d_in[7];
    const float* eps    = (const float*)d_in[8];
    const float* mlp_W1 = (const float*)d_in[9];
    const float* mlp_b1 = (const float*)d_in[10];
    const float* mlp_W2 = (const float*)d_in[11];
    const float* mlp_b2 = (const float*)d_in[12];
    const float* bn_g   = (const float*)d_in[13];
    const float* bn_b   = (const float*)d_in[14];
    const float* cls_W1 = (const float*)d_in[15];
    const float* cls_b1 = (const float*)d_in[16];
    const float* cls_W2 = (const float*)d_in[17];
    const float* cls_b2 = (const float*)d_in[18];
    float* out = (float*)d_out;

    const int TPB = 256;
    const int node_blocks = (N_NODES * HID + TPB - 1) / TPB;   // 12500
    const int edge_blocks = (N_EDGES * 16 + TPB - 1) / TPB;    // 100000

    k_node_proj<<<node_blocks, TPB>>>(x, Wn, bn);
    k_edge_proj<<<edge_blocks, TPB>>>(ea, We, be);

    for (int l = 0; l < N_LAYERS; l++) {
        k_pre<<<node_blocks, TPB>>>(eps, l);
        k_msg<<<edge_blocks, TPB>>>(ei);
        k_mlp<<<N_NODES / 8, TPB>>>(mlp_W1 + l * HID * HID, mlp_b1 + l * HID,
                                    mlp_W2 + l * HID * HID, mlp_b2 + l * HID);
        k_bnfin<<<1, 64>>>();
        k_bnapply<<<node_blocks, TPB>>>(bn_g + l * HID, bn_b + l * HID);
    }

    k_pool_zero<<<(N_GRAPHS * HID + TPB - 1) / TPB, TPB>>>();
    k_pool<<<node_blocks, TPB>>>(batch);
    k_cls<<<1, 128>>>(cls_W1, cls_b1, cls_W2, cls_b2, out);
}